// round 1
// baseline (speedup 1.0000x reference)
#include <cuda_runtime.h>
#include <cstdint>

#define N_NODES 100000
#define N_EDGES 1600000

// ---------------- scratch (device globals; no allocation allowed) ----------
__device__ float g_agg[N_NODES * 64];   // layer1 agg (64 wide); reused for layer2 (32 wide)
__device__ float g_cnt[N_NODES];
__device__ float g_h1[N_NODES * 32];
__device__ int   g_src[N_EDGES];
__device__ int   g_dst[N_EDGES];
__device__ int   g_is64;

// ---------------- JAX threefry2x32 (partitionable scheme) ------------------
struct TF2 { uint32_t a, b; };

__host__ __device__ constexpr uint32_t rotl32(uint32_t v, int r) {
    return (v << r) | (v >> (32 - r));
}

__host__ __device__ constexpr TF2 threefry(uint32_t k0, uint32_t k1,
                                           uint32_t x0, uint32_t x1) {
    const uint32_t ks0 = k0, ks1 = k1, ks2 = k0 ^ k1 ^ 0x1BD11BDAu;
    const int ra[4] = {13, 15, 26, 6};
    const int rb[4] = {17, 29, 16, 24};
    x0 += ks0; x1 += ks1;
#pragma unroll
    for (int i = 0; i < 4; i++) { x0 += x1; x1 = rotl32(x1, ra[i]); x1 ^= x0; }
    x0 += ks1; x1 += ks2 + 1u;
#pragma unroll
    for (int i = 0; i < 4; i++) { x0 += x1; x1 = rotl32(x1, rb[i]); x1 ^= x0; }
    x0 += ks2; x1 += ks0 + 2u;
#pragma unroll
    for (int i = 0; i < 4; i++) { x0 += x1; x1 = rotl32(x1, ra[i]); x1 ^= x0; }
    x0 += ks0; x1 += ks1 + 3u;
#pragma unroll
    for (int i = 0; i < 4; i++) { x0 += x1; x1 = rotl32(x1, rb[i]); x1 ^= x0; }
    x0 += ks1; x1 += ks2 + 4u;
#pragma unroll
    for (int i = 0; i < 4; i++) { x0 += x1; x1 = rotl32(x1, ra[i]); x1 ^= x0; }
    x0 += ks2; x1 += ks0 + 5u;
    return {x0, x1};
}

// dropout keys: jax.random.split(jax.random.key(42), 2), fold-like split:
//   dk[i] = threefry2x32((0,42), hi=0, lo=i)
constexpr TF2 DK0 = threefry(0u, 42u, 0u, 0u);
constexpr TF2 DK1 = threefry(0u, 42u, 0u, 1u);

// partitionable 32-bit random bits for flat index j (< 2^32): b1 ^ b2 of
// threefry(key, hi=0, lo=j). bernoulli(0.5) keep <=> uniform<0.5 <=> MSB==0.
template <uint32_t K0, uint32_t K1>
__device__ __forceinline__ bool drop_bit(uint32_t j) {
    TF2 r = threefry(K0, K1, 0u, j);
    return ((r.a ^ r.b) >> 31) != 0;   // MSB set -> u >= 0.5 -> dropped
}

// ---------------- kernels --------------------------------------------------
__global__ void k_zero1() {  // zero layer-1 agg (6.4M floats) + counts
    int i = blockIdx.x * blockDim.x + threadIdx.x;
    if (i < (N_NODES * 64) / 4)
        reinterpret_cast<float4*>(g_agg)[i] = make_float4(0.f, 0.f, 0.f, 0.f);
    if (i < N_NODES) g_cnt[i] = 0.f;
}

__global__ void k_zero2() {  // zero layer-2 agg (3.2M floats)
    int i = blockIdx.x * blockDim.x + threadIdx.x;
    if (i < (N_NODES * 32) / 4)
        reinterpret_cast<float4*>(g_agg)[i] = make_float4(0.f, 0.f, 0.f, 0.f);
}

// detect edge_index dtype: int64 has zero hi-words; int32 data ~never does
__global__ void k_detect(const uint32_t* __restrict__ e) {
    if (blockIdx.x == 0 && threadIdx.x == 0) {
        int is64 = 1;
        for (int i = 0; i < 64; i++)
            if (e[2 * i + 1] != 0u) { is64 = 0; break; }
        g_is64 = is64;
    }
}

__global__ void k_prep(const uint32_t* __restrict__ ei) {
    int e = blockIdx.x * blockDim.x + threadIdx.x;
    if (e >= N_EDGES) return;
    int s, d;
    if (g_is64) {
        s = (int)ei[2 * e];
        d = (int)ei[2 * (N_EDGES + e)];
    } else {
        s = (int)ei[e];
        d = (int)ei[N_EDGES + e];
    }
    g_src[e] = s;
    g_dst[e] = d;
    atomicAdd(&g_cnt[d], 1.0f);
}

// layer-1 scatter: 16 lanes per edge, each handles one float4 of the 64-wide row
__global__ void k_scatter1(const float* __restrict__ x) {
    int t = blockIdx.x * blockDim.x + threadIdx.x;   // < E*16 = 25.6M
    int e = t >> 4;
    int c = t & 15;
    if (e >= N_EDGES) return;
    int s = g_src[e], d = g_dst[e];
    float4 v = __ldg(reinterpret_cast<const float4*>(x + s * 64) + c);
    float* p = g_agg + d * 64 + c * 4;
    asm volatile("red.global.add.v4.f32 [%0], {%1,%2,%3,%4};"
                 :: "l"(p), "f"(v.x), "f"(v.y), "f"(v.z), "f"(v.w) : "memory");
}

// layer-2 scatter: 8 lanes per edge over the 32-wide h1 row
__global__ void k_scatter2() {
    int t = blockIdx.x * blockDim.x + threadIdx.x;   // < E*8 = 12.8M
    int e = t >> 3;
    int c = t & 7;
    if (e >= N_EDGES) return;
    int s = g_src[e], d = g_dst[e];
    float4 v = __ldg(reinterpret_cast<const float4*>(g_h1 + s * 32) + c);
    float* p = g_agg + d * 32 + c * 4;
    asm volatile("red.global.add.v4.f32 [%0], {%1,%2,%3,%4};"
                 :: "l"(p), "f"(v.x), "f"(v.y), "f"(v.z), "f"(v.w) : "memory");
}

// layer 1: h1 = dropout(leaky_relu(mean @ W1_l + b1 + x @ W1_r))
__global__ void k_combine1(const float* __restrict__ x,
                           const float* __restrict__ Wl,
                           const float* __restrict__ b,
                           const float* __restrict__ Wr) {
    __shared__ float swl[64 * 32], swr[64 * 32], rows[8][128];
    int tid = threadIdx.x;
    for (int i = tid; i < 2048; i += 256) { swl[i] = Wl[i]; swr[i] = Wr[i]; }
    int w = tid >> 5, lane = tid & 31;
    int node = blockIdx.x * 8 + w;                    // grid = 12500 exact
    float inv = 1.0f / fmaxf(g_cnt[node], 1.0f);
    rows[w][lane]       = g_agg[node * 64 + lane] * inv;
    rows[w][32 + lane]  = g_agg[node * 64 + 32 + lane] * inv;
    rows[w][64 + lane]  = x[node * 64 + lane];
    rows[w][96 + lane]  = x[node * 64 + 32 + lane];
    __syncthreads();
    float acc = b[lane];
#pragma unroll
    for (int k = 0; k < 64; k++)
        acc = fmaf(rows[w][k], swl[k * 32 + lane],
              fmaf(rows[w][64 + k], swr[k * 32 + lane], acc));
    acc = acc > 0.f ? acc : 0.01f * acc;              // leaky relu
    uint32_t j = (uint32_t)(node * 32 + lane);
    acc = drop_bit<DK0.a, DK0.b>(j) ? 0.f : 2.0f * acc;
    g_h1[node * 32 + lane] = acc;
}

// layer 2: out = l2norm(dropout(mean2 @ W2_l + b2 + h1 @ W2_r))
__global__ void k_combine2(const float* __restrict__ Wl,
                           const float* __restrict__ b,
                           const float* __restrict__ Wr,
                           float* __restrict__ out) {
    __shared__ float swl[32 * 64], swr[32 * 64], rows[8][64];
    int tid = threadIdx.x;
    for (int i = tid; i < 2048; i += 256) { swl[i] = Wl[i]; swr[i] = Wr[i]; }
    int w = tid >> 5, lane = tid & 31;
    int node = blockIdx.x * 8 + w;                    // grid = 12500 exact
    float inv = 1.0f / fmaxf(g_cnt[node], 1.0f);
    rows[w][lane]      = g_agg[node * 32 + lane] * inv;
    rows[w][32 + lane] = g_h1[node * 32 + lane];
    __syncthreads();
    float a0 = b[lane], a1 = b[32 + lane];
#pragma unroll
    for (int k = 0; k < 32; k++) {
        float m = rows[w][k], h = rows[w][32 + k];
        a0 = fmaf(m, swl[k * 64 + lane],      fmaf(h, swr[k * 64 + lane],      a0));
        a1 = fmaf(m, swl[k * 64 + 32 + lane], fmaf(h, swr[k * 64 + 32 + lane], a1));
    }
    uint32_t j0 = (uint32_t)(node * 64 + lane);
    a0 = drop_bit<DK1.a, DK1.b>(j0)       ? 0.f : 2.0f * a0;
    a1 = drop_bit<DK1.a, DK1.b>(j0 + 32u) ? 0.f : 2.0f * a1;
    float ss = a0 * a0 + a1 * a1;
#pragma unroll
    for (int o = 16; o > 0; o >>= 1)
        ss += __shfl_xor_sync(0xffffffffu, ss, o);
    float scale = 1.0f / fmaxf(sqrtf(ss), 1e-12f);
    out[node * 64 + lane]      = a0 * scale;
    out[node * 64 + 32 + lane] = a1 * scale;
}

// ---------------- launch ----------------------------------------------------
extern "C" void kernel_launch(void* const* d_in, const int* in_sizes, int n_in,
                              void* d_out, int out_size) {
    const float*    x   = (const float*)d_in[0];
    const uint32_t* ei  = (const uint32_t*)d_in[1];   // int32 or int64 (detected)
    const float*    W1l = (const float*)d_in[2];
    const float*    b1  = (const float*)d_in[3];
    const float*    W1r = (const float*)d_in[4];
    const float*    W2l = (const float*)d_in[5];
    const float*    b2  = (const float*)d_in[6];
    const float*    W2r = (const float*)d_in[7];
    float* out = (float*)d_out;

    k_zero1<<<6250, 256>>>();
    k_detect<<<1, 32>>>(ei);
    k_prep<<<(N_EDGES + 255) / 256, 256>>>(ei);
    k_scatter1<<<(N_EDGES * 16) / 256, 256>>>(x);          // 100000 blocks
    k_combine1<<<N_NODES / 8, 256>>>(x, W1l, b1, W1r);     // 12500 blocks
    k_zero2<<<3125, 256>>>();
    k_scatter2<<<(N_EDGES * 8) / 256, 256>>>();            // 50000 blocks
    k_combine2<<<N_NODES / 8, 256>>>(W2l, b2, W2r, out);   // 12500 blocks
}

// round 2
// speedup vs baseline: 1.1596x; 1.1596x over previous
#include <cuda_runtime.h>
#include <cstdint>

#define N_NODES 100000
#define N_EDGES 1600000

// ---------------- scratch (device globals; no allocation allowed) ----------
__device__ float g_y[N_NODES * 32];     // x @ W1_l
__device__ float g_agg[N_NODES * 32];   // layer1 scatter target (projected space)
__device__ float g_agg2[N_NODES * 32];  // layer2 scatter target
__device__ float g_cnt[N_NODES];
__device__ float g_h1[N_NODES * 32];
__device__ int   g_src[N_EDGES];
__device__ int   g_dst[N_EDGES];
__device__ int   g_is64;

// ---------------- JAX threefry2x32 (partitionable scheme) ------------------
struct TF2 { uint32_t a, b; };

__host__ __device__ constexpr uint32_t rotl32(uint32_t v, int r) {
    return (v << r) | (v >> (32 - r));
}

__host__ __device__ constexpr TF2 threefry(uint32_t k0, uint32_t k1,
                                           uint32_t x0, uint32_t x1) {
    const uint32_t ks0 = k0, ks1 = k1, ks2 = k0 ^ k1 ^ 0x1BD11BDAu;
    const int ra[4] = {13, 15, 26, 6};
    const int rb[4] = {17, 29, 16, 24};
    x0 += ks0; x1 += ks1;
#pragma unroll
    for (int i = 0; i < 4; i++) { x0 += x1; x1 = rotl32(x1, ra[i]); x1 ^= x0; }
    x0 += ks1; x1 += ks2 + 1u;
#pragma unroll
    for (int i = 0; i < 4; i++) { x0 += x1; x1 = rotl32(x1, rb[i]); x1 ^= x0; }
    x0 += ks2; x1 += ks0 + 2u;
#pragma unroll
    for (int i = 0; i < 4; i++) { x0 += x1; x1 = rotl32(x1, ra[i]); x1 ^= x0; }
    x0 += ks0; x1 += ks1 + 3u;
#pragma unroll
    for (int i = 0; i < 4; i++) { x0 += x1; x1 = rotl32(x1, rb[i]); x1 ^= x0; }
    x0 += ks1; x1 += ks2 + 4u;
#pragma unroll
    for (int i = 0; i < 4; i++) { x0 += x1; x1 = rotl32(x1, ra[i]); x1 ^= x0; }
    x0 += ks2; x1 += ks0 + 5u;
    return {x0, x1};
}

constexpr TF2 DK0 = threefry(0u, 42u, 0u, 0u);
constexpr TF2 DK1 = threefry(0u, 42u, 0u, 1u);

template <uint32_t K0, uint32_t K1>
__device__ __forceinline__ bool drop_bit(uint32_t j) {
    TF2 r = threefry(K0, K1, 0u, j);
    return ((r.a ^ r.b) >> 31) != 0;   // MSB set -> u >= 0.5 -> dropped
}

// ---------------- kernels --------------------------------------------------
// detect edge_index dtype: int64 has zero hi-words; int32 data ~never does
__global__ void k_detect(const uint32_t* __restrict__ e) {
    if (blockIdx.x == 0 && threadIdx.x == 0) {
        int is64 = 1;
        for (int i = 0; i < 64; i++)
            if (e[2 * i + 1] != 0u) { is64 = 0; break; }
        g_is64 = is64;
    }
}

// fused: y = x @ W1_l (64->32), zero g_agg row + g_cnt
__global__ void k_pre(const float* __restrict__ x,
                      const float* __restrict__ Wl) {
    __shared__ float swl[64 * 32], rows[8][64];
    int tid = threadIdx.x;
    for (int i = tid; i < 2048; i += 256) swl[i] = Wl[i];
    int w = tid >> 5, lane = tid & 31;
    int node = blockIdx.x * 8 + w;                    // grid = 12500 exact
    rows[w][lane]      = x[node * 64 + lane];
    rows[w][32 + lane] = x[node * 64 + 32 + lane];
    __syncthreads();
    float acc = 0.f;
#pragma unroll
    for (int k = 0; k < 64; k++)
        acc = fmaf(rows[w][k], swl[k * 32 + lane], acc);
    g_y[node * 32 + lane]   = acc;
    g_agg[node * 32 + lane] = 0.f;
    if (lane == 0) g_cnt[node] = 0.f;
}

__global__ void k_prep(const uint32_t* __restrict__ ei) {
    int e = blockIdx.x * blockDim.x + threadIdx.x;
    if (e >= N_EDGES) return;
    int s, d;
    if (g_is64) {
        uint2 sv = reinterpret_cast<const uint2*>(ei)[e];
        uint2 dv = reinterpret_cast<const uint2*>(ei)[N_EDGES + e];
        s = (int)sv.x; d = (int)dv.x;
    } else {
        s = (int)ei[e];
        d = (int)ei[N_EDGES + e];
    }
    g_src[e] = s;
    g_dst[e] = d;
    atomicAdd(&g_cnt[d], 1.0f);
}

// layer-1 scatter in projected (32-wide) space: 8 lanes per edge
__global__ void k_scatter1() {
    int t = blockIdx.x * blockDim.x + threadIdx.x;   // < E*8 = 12.8M
    int e = t >> 3;
    int c = t & 7;
    if (e >= N_EDGES) return;
    int s = g_src[e], d = g_dst[e];
    float4 v = __ldg(reinterpret_cast<const float4*>(g_y + s * 32) + c);
    float* p = g_agg + d * 32 + c * 4;
    asm volatile("red.global.add.v4.f32 [%0], {%1,%2,%3,%4};"
                 :: "l"(p), "f"(v.x), "f"(v.y), "f"(v.z), "f"(v.w) : "memory");
}

// layer-2 scatter: 8 lanes per edge over the 32-wide h1 row
__global__ void k_scatter2() {
    int t = blockIdx.x * blockDim.x + threadIdx.x;   // < E*8 = 12.8M
    int e = t >> 3;
    int c = t & 7;
    if (e >= N_EDGES) return;
    int s = g_src[e], d = g_dst[e];
    float4 v = __ldg(reinterpret_cast<const float4*>(g_h1 + s * 32) + c);
    float* p = g_agg2 + d * 32 + c * 4;
    asm volatile("red.global.add.v4.f32 [%0], {%1,%2,%3,%4};"
                 :: "l"(p), "f"(v.x), "f"(v.y), "f"(v.z), "f"(v.w) : "memory");
}

// layer 1: h1 = dropout(leaky_relu(agg*inv + b1 + x @ W1_r)); zero g_agg2
__global__ void k_combine1(const float* __restrict__ x,
                           const float* __restrict__ b,
                           const float* __restrict__ Wr) {
    __shared__ float swr[64 * 32], rows[8][64];
    int tid = threadIdx.x;
    for (int i = tid; i < 2048; i += 256) swr[i] = Wr[i];
    int w = tid >> 5, lane = tid & 31;
    int node = blockIdx.x * 8 + w;                    // grid = 12500 exact
    rows[w][lane]      = x[node * 64 + lane];
    rows[w][32 + lane] = x[node * 64 + 32 + lane];
    __syncthreads();
    float inv = 1.0f / fmaxf(g_cnt[node], 1.0f);
    float acc = fmaf(g_agg[node * 32 + lane], inv, b[lane]);
#pragma unroll
    for (int k = 0; k < 64; k++)
        acc = fmaf(rows[w][k], swr[k * 32 + lane], acc);
    acc = acc > 0.f ? acc : 0.01f * acc;              // leaky relu
    uint32_t j = (uint32_t)(node * 32 + lane);
    acc = drop_bit<DK0.a, DK0.b>(j) ? 0.f : 2.0f * acc;
    g_h1[node * 32 + lane]   = acc;
    g_agg2[node * 32 + lane] = 0.f;                   // pre-zero layer-2 target
}

// layer 2: out = l2norm(dropout(mean2 @ W2_l + b2 + h1 @ W2_r))
__global__ void k_combine2(const float* __restrict__ Wl,
                           const float* __restrict__ b,
                           const float* __restrict__ Wr,
                           float* __restrict__ out) {
    __shared__ float swl[32 * 64], swr[32 * 64], rows[8][64];
    int tid = threadIdx.x;
    for (int i = tid; i < 2048; i += 256) { swl[i] = Wl[i]; swr[i] = Wr[i]; }
    int w = tid >> 5, lane = tid & 31;
    int node = blockIdx.x * 8 + w;                    // grid = 12500 exact
    float inv = 1.0f / fmaxf(g_cnt[node], 1.0f);
    rows[w][lane]      = g_agg2[node * 32 + lane] * inv;
    rows[w][32 + lane] = g_h1[node * 32 + lane];
    __syncthreads();
    float a0 = b[lane], a1 = b[32 + lane];
#pragma unroll
    for (int k = 0; k < 32; k++) {
        float m = rows[w][k], h = rows[w][32 + k];
        a0 = fmaf(m, swl[k * 64 + lane],      fmaf(h, swr[k * 64 + lane],      a0));
        a1 = fmaf(m, swl[k * 64 + 32 + lane], fmaf(h, swr[k * 64 + 32 + lane], a1));
    }
    uint32_t j0 = (uint32_t)(node * 64 + lane);
    a0 = drop_bit<DK1.a, DK1.b>(j0)       ? 0.f : 2.0f * a0;
    a1 = drop_bit<DK1.a, DK1.b>(j0 + 32u) ? 0.f : 2.0f * a1;
    float ss = a0 * a0 + a1 * a1;
#pragma unroll
    for (int o = 16; o > 0; o >>= 1)
        ss += __shfl_xor_sync(0xffffffffu, ss, o);
    float scale = 1.0f / fmaxf(sqrtf(ss), 1e-12f);
    out[node * 64 + lane]      = a0 * scale;
    out[node * 64 + 32 + lane] = a1 * scale;
}

// ---------------- launch ----------------------------------------------------
extern "C" void kernel_launch(void* const* d_in, const int* in_sizes, int n_in,
                              void* d_out, int out_size) {
    const float*    x   = (const float*)d_in[0];
    const uint32_t* ei  = (const uint32_t*)d_in[1];   // int32 or int64 (detected)
    const float*    W1l = (const float*)d_in[2];
    const float*    b1  = (const float*)d_in[3];
    const float*    W1r = (const float*)d_in[4];
    const float*    W2l = (const float*)d_in[5];
    const float*    b2  = (const float*)d_in[6];
    const float*    W2r = (const float*)d_in[7];
    float* out = (float*)d_out;

    k_detect<<<1, 32>>>(ei);
    k_pre<<<N_NODES / 8, 256>>>(x, W1l);               // 12500 blocks
    k_prep<<<(N_EDGES + 255) / 256, 256>>>(ei);        // 6250 blocks
    k_scatter1<<<(N_EDGES * 8) / 256, 256>>>();        // 50000 blocks
    k_combine1<<<N_NODES / 8, 256>>>(x, b1, W1r);      // 12500 blocks
    k_scatter2<<<(N_EDGES * 8) / 256, 256>>>();        // 50000 blocks
    k_combine2<<<N_NODES / 8, 256>>>(W2l, b2, W2r, out);
}

// round 3
// speedup vs baseline: 1.2638x; 1.0898x over previous
#include <cuda_runtime.h>
#include <cstdint>

#define N_NODES 100000
#define N_EDGES 1600000

// ---------------- scratch (device globals; no allocation allowed) ----------
__device__ float g_y[N_NODES * 32];     // x @ W1_l
__device__ float g_z[N_NODES * 32];     // x @ W1_r
__device__ float g_agg[N_NODES * 32];   // layer1 scatter target (projected space)
__device__ float g_agg2[N_NODES * 32];  // layer2 scatter target
__device__ float g_cnt[N_NODES];
__device__ float g_h1[N_NODES * 32];
__device__ int2  g_edge[N_EDGES];       // packed (src, dst)
__device__ int   g_is64;

// ---------------- JAX threefry2x32 (partitionable scheme) ------------------
struct TF2 { uint32_t a, b; };

__host__ __device__ constexpr uint32_t rotl32(uint32_t v, int r) {
    return (v << r) | (v >> (32 - r));
}

__host__ __device__ constexpr TF2 threefry(uint32_t k0, uint32_t k1,
                                           uint32_t x0, uint32_t x1) {
    const uint32_t ks0 = k0, ks1 = k1, ks2 = k0 ^ k1 ^ 0x1BD11BDAu;
    const int ra[4] = {13, 15, 26, 6};
    const int rb[4] = {17, 29, 16, 24};
    x0 += ks0; x1 += ks1;
#pragma unroll
    for (int i = 0; i < 4; i++) { x0 += x1; x1 = rotl32(x1, ra[i]); x1 ^= x0; }
    x0 += ks1; x1 += ks2 + 1u;
#pragma unroll
    for (int i = 0; i < 4; i++) { x0 += x1; x1 = rotl32(x1, rb[i]); x1 ^= x0; }
    x0 += ks2; x1 += ks0 + 2u;
#pragma unroll
    for (int i = 0; i < 4; i++) { x0 += x1; x1 = rotl32(x1, ra[i]); x1 ^= x0; }
    x0 += ks0; x1 += ks1 + 3u;
#pragma unroll
    for (int i = 0; i < 4; i++) { x0 += x1; x1 = rotl32(x1, rb[i]); x1 ^= x0; }
    x0 += ks1; x1 += ks2 + 4u;
#pragma unroll
    for (int i = 0; i < 4; i++) { x0 += x1; x1 = rotl32(x1, ra[i]); x1 ^= x0; }
    x0 += ks2; x1 += ks0 + 5u;
    return {x0, x1};
}

constexpr TF2 DK0 = threefry(0u, 42u, 0u, 0u);
constexpr TF2 DK1 = threefry(0u, 42u, 0u, 1u);

template <uint32_t K0, uint32_t K1>
__device__ __forceinline__ bool drop_bit(uint32_t j) {
    TF2 r = threefry(K0, K1, 0u, j);
    return ((r.a ^ r.b) >> 31) != 0;   // MSB set -> u >= 0.5 -> dropped
}

// ---------------- kernels --------------------------------------------------
__global__ void k_detect(const uint32_t* __restrict__ e) {
    if (blockIdx.x == 0 && threadIdx.x == 0) {
        int is64 = 1;
        for (int i = 0; i < 64; i++)
            if (e[2 * i + 1] != 0u) { is64 = 0; break; }
        g_is64 = is64;
    }
}

// fused: y = x @ W1_l, z = x @ W1_r (64->32 each), zero g_agg + g_cnt
__global__ void k_pre(const float* __restrict__ x,
                      const float* __restrict__ Wl,
                      const float* __restrict__ Wr) {
    __shared__ float swl[64 * 32], swr[64 * 32], rows[8][64];
    int tid = threadIdx.x;
    for (int i = tid; i < 2048; i += 256) { swl[i] = Wl[i]; swr[i] = Wr[i]; }
    int w = tid >> 5, lane = tid & 31;
    int node = blockIdx.x * 8 + w;                    // grid = 12500 exact
    rows[w][lane]      = x[node * 64 + lane];
    rows[w][32 + lane] = x[node * 64 + 32 + lane];
    __syncthreads();
    float accl = 0.f, accr = 0.f;
#pragma unroll
    for (int k = 0; k < 64; k++) {
        float xv = rows[w][k];
        accl = fmaf(xv, swl[k * 32 + lane], accl);
        accr = fmaf(xv, swr[k * 32 + lane], accr);
    }
    g_y[node * 32 + lane]   = accl;
    g_z[node * 32 + lane]   = accr;
    g_agg[node * 32 + lane] = 0.f;
    if (lane == 0) g_cnt[node] = 0.f;
}

__global__ void k_prep(const uint32_t* __restrict__ ei) {
    int e = blockIdx.x * blockDim.x + threadIdx.x;
    if (e >= N_EDGES) return;
    int s, d;
    if (g_is64) {
        uint2 sv = reinterpret_cast<const uint2*>(ei)[e];
        uint2 dv = reinterpret_cast<const uint2*>(ei)[N_EDGES + e];
        s = (int)sv.x; d = (int)dv.x;
    } else {
        s = (int)ei[e];
        d = (int)ei[N_EDGES + e];
    }
    g_edge[e] = make_int2(s, d);
    atomicAdd(&g_cnt[d], 1.0f);
}

// scatter with ILP=4: each thread handles column c (of 8) for 4 consecutive
// edges. grid covers E/4 edge-groups * 8 columns.
template <bool LAYER1>
__global__ void k_scatter() {
    int t = blockIdx.x * blockDim.x + threadIdx.x;   // < (E/4)*8 = 3.2M
    int c  = t & 7;
    int eb = t >> 3;                                  // edge group, 4 edges
    const float* srcbuf = LAYER1 ? g_y : g_h1;
    float*       dstbuf = LAYER1 ? g_agg : g_agg2;
    int4 p01 = reinterpret_cast<const int4*>(g_edge)[eb * 2];
    int4 p23 = reinterpret_cast<const int4*>(g_edge)[eb * 2 + 1];
    float4 v0 = __ldg(reinterpret_cast<const float4*>(srcbuf + p01.x * 32) + c);
    float4 v1 = __ldg(reinterpret_cast<const float4*>(srcbuf + p01.z * 32) + c);
    float4 v2 = __ldg(reinterpret_cast<const float4*>(srcbuf + p23.x * 32) + c);
    float4 v3 = __ldg(reinterpret_cast<const float4*>(srcbuf + p23.z * 32) + c);
    float* q0 = dstbuf + p01.y * 32 + c * 4;
    float* q1 = dstbuf + p01.w * 32 + c * 4;
    float* q2 = dstbuf + p23.y * 32 + c * 4;
    float* q3 = dstbuf + p23.w * 32 + c * 4;
    asm volatile("red.global.add.v4.f32 [%0], {%1,%2,%3,%4};"
                 :: "l"(q0), "f"(v0.x), "f"(v0.y), "f"(v0.z), "f"(v0.w) : "memory");
    asm volatile("red.global.add.v4.f32 [%0], {%1,%2,%3,%4};"
                 :: "l"(q1), "f"(v1.x), "f"(v1.y), "f"(v1.z), "f"(v1.w) : "memory");
    asm volatile("red.global.add.v4.f32 [%0], {%1,%2,%3,%4};"
                 :: "l"(q2), "f"(v2.x), "f"(v2.y), "f"(v2.z), "f"(v2.w) : "memory");
    asm volatile("red.global.add.v4.f32 [%0], {%1,%2,%3,%4};"
                 :: "l"(q3), "f"(v3.x), "f"(v3.y), "f"(v3.z), "f"(v3.w) : "memory");
}

// layer 1 elementwise: h1 = dropout(leaky_relu(agg*inv + b1 + z)); zero agg2
__global__ void k_combine1(const float* __restrict__ b) {
    int i = blockIdx.x * blockDim.x + threadIdx.x;   // < 800000 (float4 units)
    int j = i * 4;
    int node = j >> 5;
    int col  = j & 31;
    float inv = 1.0f / fmaxf(g_cnt[node], 1.0f);
    float4 a = reinterpret_cast<const float4*>(g_agg)[i];
    float4 z = reinterpret_cast<const float4*>(g_z)[i];
    float4 bb = *reinterpret_cast<const float4*>(b + col);
    float r[4] = {fmaf(a.x, inv, bb.x + z.x), fmaf(a.y, inv, bb.y + z.y),
                  fmaf(a.z, inv, bb.z + z.z), fmaf(a.w, inv, bb.w + z.w)};
    float4 o;
    float* po = &o.x;
#pragma unroll
    for (int k = 0; k < 4; k++) {
        float v = r[k];
        v = v > 0.f ? v : 0.01f * v;
        po[k] = drop_bit<DK0.a, DK0.b>((uint32_t)(j + k)) ? 0.f : 2.0f * v;
    }
    reinterpret_cast<float4*>(g_h1)[i] = o;
    reinterpret_cast<float4*>(g_agg2)[i] = make_float4(0.f, 0.f, 0.f, 0.f);
}

// layer 2: out = l2norm(dropout(mean2 @ W2_l + b2 + h1 @ W2_r))
__global__ void k_combine2(const float* __restrict__ Wl,
                           const float* __restrict__ b,
                           const float* __restrict__ Wr,
                           float* __restrict__ out) {
    __shared__ float swl[32 * 64], swr[32 * 64], rows[8][64];
    int tid = threadIdx.x;
    for (int i = tid; i < 2048; i += 256) { swl[i] = Wl[i]; swr[i] = Wr[i]; }
    int w = tid >> 5, lane = tid & 31;
    int node = blockIdx.x * 8 + w;                    // grid = 12500 exact
    float inv = 1.0f / fmaxf(g_cnt[node], 1.0f);
    rows[w][lane]      = g_agg2[node * 32 + lane] * inv;
    rows[w][32 + lane] = g_h1[node * 32 + lane];
    __syncthreads();
    float a0 = b[lane], a1 = b[32 + lane];
#pragma unroll
    for (int k = 0; k < 32; k++) {
        float m = rows[w][k], h = rows[w][32 + k];
        a0 = fmaf(m, swl[k * 64 + lane],      fmaf(h, swr[k * 64 + lane],      a0));
        a1 = fmaf(m, swl[k * 64 + 32 + lane], fmaf(h, swr[k * 64 + 32 + lane], a1));
    }
    uint32_t j0 = (uint32_t)(node * 64 + lane);
    a0 = drop_bit<DK1.a, DK1.b>(j0)       ? 0.f : 2.0f * a0;
    a1 = drop_bit<DK1.a, DK1.b>(j0 + 32u) ? 0.f : 2.0f * a1;
    float ss = a0 * a0 + a1 * a1;
#pragma unroll
    for (int o = 16; o > 0; o >>= 1)
        ss += __shfl_xor_sync(0xffffffffu, ss, o);
    float scale = 1.0f / fmaxf(sqrtf(ss), 1e-12f);
    out[node * 64 + lane]      = a0 * scale;
    out[node * 64 + 32 + lane] = a1 * scale;
}

// ---------------- launch ----------------------------------------------------
extern "C" void kernel_launch(void* const* d_in, const int* in_sizes, int n_in,
                              void* d_out, int out_size) {
    const float*    x   = (const float*)d_in[0];
    const uint32_t* ei  = (const uint32_t*)d_in[1];   // int32 or int64 (detected)
    const float*    W1l = (const float*)d_in[2];
    const float*    b1  = (const float*)d_in[3];
    const float*    W1r = (const float*)d_in[4];
    const float*    W2l = (const float*)d_in[5];
    const float*    b2  = (const float*)d_in[6];
    const float*    W2r = (const float*)d_in[7];
    float* out = (float*)d_out;

    k_detect<<<1, 32>>>(ei);
    k_pre<<<N_NODES / 8, 256>>>(x, W1l, W1r);          // 12500 blocks
    k_prep<<<(N_EDGES + 255) / 256, 256>>>(ei);        // 6250 blocks
    k_scatter<true><<<(N_EDGES / 4 * 8) / 256, 256>>>();   // 12500 blocks
    k_combine1<<<(N_NODES * 32 / 4) / 256, 256>>>(b1);     // 3125 blocks
    k_scatter<false><<<(N_EDGES / 4 * 8) / 256, 256>>>();  // 12500 blocks
    k_combine2<<<N_NODES / 8, 256>>>(W2l, b2, W2r, out);   // 12500 blocks
}

// round 4
// speedup vs baseline: 1.3220x; 1.0461x over previous
#include <cuda_runtime.h>
#include <cstdint>

#define N_NODES 100000
#define N_EDGES 1600000
#define SCAN_BLK 512
#define NSCAN_BLKS 196   // 196*512 = 100352 >= N_NODES

// ---------------- scratch (device globals; no allocation allowed) ----------
__device__ float g_y[N_NODES * 32];     // x @ W1_l
__device__ float g_z[N_NODES * 32];     // x @ W1_r
__device__ float g_h1[N_NODES * 32];
__device__ int2  g_edge[N_EDGES];       // packed (src, dst)
__device__ int   g_csr[N_EDGES];        // src ids grouped by dst
__device__ int   g_off[N_NODES + 1];    // counts -> exclusive offsets
__device__ int   g_part[N_NODES];       // scan partials
__device__ int   g_cur[N_NODES];        // bucket cursors
__device__ int   g_bsum[256];
__device__ int   g_is64;

// ---------------- JAX threefry2x32 (partitionable scheme) ------------------
struct TF2 { uint32_t a, b; };

__host__ __device__ constexpr uint32_t rotl32(uint32_t v, int r) {
    return (v << r) | (v >> (32 - r));
}

__host__ __device__ constexpr TF2 threefry(uint32_t k0, uint32_t k1,
                                           uint32_t x0, uint32_t x1) {
    const uint32_t ks0 = k0, ks1 = k1, ks2 = k0 ^ k1 ^ 0x1BD11BDAu;
    const int ra[4] = {13, 15, 26, 6};
    const int rb[4] = {17, 29, 16, 24};
    x0 += ks0; x1 += ks1;
#pragma unroll
    for (int i = 0; i < 4; i++) { x0 += x1; x1 = rotl32(x1, ra[i]); x1 ^= x0; }
    x0 += ks1; x1 += ks2 + 1u;
#pragma unroll
    for (int i = 0; i < 4; i++) { x0 += x1; x1 = rotl32(x1, rb[i]); x1 ^= x0; }
    x0 += ks2; x1 += ks0 + 2u;
#pragma unroll
    for (int i = 0; i < 4; i++) { x0 += x1; x1 = rotl32(x1, ra[i]); x1 ^= x0; }
    x0 += ks0; x1 += ks1 + 3u;
#pragma unroll
    for (int i = 0; i < 4; i++) { x0 += x1; x1 = rotl32(x1, rb[i]); x1 ^= x0; }
    x0 += ks1; x1 += ks2 + 4u;
#pragma unroll
    for (int i = 0; i < 4; i++) { x0 += x1; x1 = rotl32(x1, ra[i]); x1 ^= x0; }
    x0 += ks2; x1 += ks0 + 5u;
    return {x0, x1};
}

constexpr TF2 DK0 = threefry(0u, 42u, 0u, 0u);
constexpr TF2 DK1 = threefry(0u, 42u, 0u, 1u);

template <uint32_t K0, uint32_t K1>
__device__ __forceinline__ bool drop_bit(uint32_t j) {
    TF2 r = threefry(K0, K1, 0u, j);
    return ((r.a ^ r.b) >> 31) != 0;   // MSB set -> u >= 0.5 -> dropped
}

// ---------------- kernels --------------------------------------------------
__global__ void k_detect(const uint32_t* __restrict__ e) {
    if (blockIdx.x == 0 && threadIdx.x == 0) {
        int is64 = 1;
        for (int i = 0; i < 64; i++)
            if (e[2 * i + 1] != 0u) { is64 = 0; break; }
        g_is64 = is64;
    }
}

// fused: y = x @ W1_l, z = x @ W1_r (64->32 each); zero g_off histogram
__global__ void k_pre(const float* __restrict__ x,
                      const float* __restrict__ Wl,
                      const float* __restrict__ Wr) {
    __shared__ float swl[64 * 32], swr[64 * 32], rows[8][64];
    int tid = threadIdx.x;
    for (int i = tid; i < 2048; i += 256) { swl[i] = Wl[i]; swr[i] = Wr[i]; }
    int gt = blockIdx.x * 256 + tid;
    if (gt < N_NODES) g_off[gt] = 0;
    int w = tid >> 5, lane = tid & 31;
    int node = blockIdx.x * 8 + w;                    // grid = 12500 exact
    rows[w][lane]      = x[node * 64 + lane];
    rows[w][32 + lane] = x[node * 64 + 32 + lane];
    __syncthreads();
    float accl = 0.f, accr = 0.f;
#pragma unroll
    for (int k = 0; k < 64; k++) {
        float xv = rows[w][k];
        accl = fmaf(xv, swl[k * 32 + lane], accl);
        accr = fmaf(xv, swr[k * 32 + lane], accr);
    }
    g_y[node * 32 + lane] = accl;
    g_z[node * 32 + lane] = accr;
}

// pack edges + dst histogram
__global__ void k_prep(const uint32_t* __restrict__ ei) {
    int e = blockIdx.x * blockDim.x + threadIdx.x;
    if (e >= N_EDGES) return;
    int s, d;
    if (g_is64) {
        uint2 sv = reinterpret_cast<const uint2*>(ei)[e];
        uint2 dv = reinterpret_cast<const uint2*>(ei)[N_EDGES + e];
        s = (int)sv.x; d = (int)dv.x;
    } else {
        s = (int)ei[e];
        d = (int)ei[N_EDGES + e];
    }
    g_edge[e] = make_int2(s, d);
    atomicAdd(&g_off[d], 1);
}

// exclusive scan over 100k counts: 3 tiny kernels
__global__ void k_scan_a() {
    __shared__ int sh[SCAN_BLK];
    int i = blockIdx.x * SCAN_BLK + threadIdx.x;
    int v = (i < N_NODES) ? g_off[i] : 0;
    sh[threadIdx.x] = v;
    __syncthreads();
    for (int o = 1; o < SCAN_BLK; o <<= 1) {
        int t = (threadIdx.x >= o) ? sh[threadIdx.x - o] : 0;
        __syncthreads();
        sh[threadIdx.x] += t;
        __syncthreads();
    }
    if (i < N_NODES) g_part[i] = sh[threadIdx.x] - v;    // exclusive in-block
    if (threadIdx.x == SCAN_BLK - 1) g_bsum[blockIdx.x] = sh[threadIdx.x];
}

__global__ void k_scan_b() {                             // 1 block of 256
    __shared__ int sh[256];
    int v = (threadIdx.x < NSCAN_BLKS) ? g_bsum[threadIdx.x] : 0;
    sh[threadIdx.x] = v;
    __syncthreads();
    for (int o = 1; o < 256; o <<= 1) {
        int t = (threadIdx.x >= o) ? sh[threadIdx.x - o] : 0;
        __syncthreads();
        sh[threadIdx.x] += t;
        __syncthreads();
    }
    if (threadIdx.x < NSCAN_BLKS) g_bsum[threadIdx.x] = sh[threadIdx.x] - v;
}

__global__ void k_scan_c() {
    int i = blockIdx.x * SCAN_BLK + threadIdx.x;
    if (i < N_NODES) {
        int o = g_part[i] + g_bsum[i / SCAN_BLK];
        g_off[i] = o;
        g_cur[i] = o;
    }
    if (i == 0) g_off[N_NODES] = N_EDGES;
}

__global__ void k_bucket() {
    int e = blockIdx.x * blockDim.x + threadIdx.x;
    if (e >= N_EDGES) return;
    int2 p = g_edge[e];
    int pos = atomicAdd(&g_cur[p.y], 1);
    g_csr[pos] = p.x;
}

// layer 1: warp per node; gather-sum y rows over CSR, fuse bias+z+lrelu+dropout
__global__ void k_agg1(const float* __restrict__ b) {
    int w = threadIdx.x >> 5, lane = threadIdx.x & 31;
    int node = blockIdx.x * 8 + w;                    // grid = 12500 exact
    int beg = g_off[node], end = g_off[node + 1];
    float acc = 0.f;
    int j = beg;
    for (; j + 4 <= end; j += 4) {
        int s0 = __ldg(g_csr + j),     s1 = __ldg(g_csr + j + 1);
        int s2 = __ldg(g_csr + j + 2), s3 = __ldg(g_csr + j + 3);
        float v0 = __ldg(g_y + s0 * 32 + lane);
        float v1 = __ldg(g_y + s1 * 32 + lane);
        float v2 = __ldg(g_y + s2 * 32 + lane);
        float v3 = __ldg(g_y + s3 * 32 + lane);
        acc += (v0 + v1) + (v2 + v3);
    }
    for (; j < end; j++)
        acc += __ldg(g_y + __ldg(g_csr + j) * 32 + lane);
    float inv = 1.0f / fmaxf((float)(end - beg), 1.0f);
    float v = fmaf(acc, inv, b[lane] + g_z[node * 32 + lane]);
    v = v > 0.f ? v : 0.01f * v;
    uint32_t jj = (uint32_t)(node * 32 + lane);
    g_h1[jj] = drop_bit<DK0.a, DK0.b>(jj) ? 0.f : 2.0f * v;
}

// layer 2 fused: gather-mean h1 rows, per-node GEMMs, dropout, l2norm
__global__ void k_agg2(const float* __restrict__ Wl,
                       const float* __restrict__ b,
                       const float* __restrict__ Wr,
                       float* __restrict__ out) {
    __shared__ float swl[32 * 64], swr[32 * 64], rows[8][64];
    int tid = threadIdx.x;
    for (int i = tid; i < 2048; i += 256) { swl[i] = Wl[i]; swr[i] = Wr[i]; }
    __syncthreads();
    int w = tid >> 5, lane = tid & 31;
    int node = blockIdx.x * 8 + w;                    // grid = 12500 exact
    int beg = g_off[node], end = g_off[node + 1];
    float acc = 0.f;
    int j = beg;
    for (; j + 4 <= end; j += 4) {
        int s0 = __ldg(g_csr + j),     s1 = __ldg(g_csr + j + 1);
        int s2 = __ldg(g_csr + j + 2), s3 = __ldg(g_csr + j + 3);
        float v0 = __ldg(g_h1 + s0 * 32 + lane);
        float v1 = __ldg(g_h1 + s1 * 32 + lane);
        float v2 = __ldg(g_h1 + s2 * 32 + lane);
        float v3 = __ldg(g_h1 + s3 * 32 + lane);
        acc += (v0 + v1) + (v2 + v3);
    }
    for (; j < end; j++)
        acc += __ldg(g_h1 + __ldg(g_csr + j) * 32 + lane);
    float inv = 1.0f / fmaxf((float)(end - beg), 1.0f);
    rows[w][lane]      = acc * inv;
    rows[w][32 + lane] = g_h1[node * 32 + lane];
    __syncwarp();
    float a0 = b[lane], a1 = b[32 + lane];
#pragma unroll
    for (int k = 0; k < 32; k++) {
        float m = rows[w][k], h = rows[w][32 + k];
        a0 = fmaf(m, swl[k * 64 + lane],      fmaf(h, swr[k * 64 + lane],      a0));
        a1 = fmaf(m, swl[k * 64 + 32 + lane], fmaf(h, swr[k * 64 + 32 + lane], a1));
    }
    uint32_t j0 = (uint32_t)(node * 64 + lane);
    a0 = drop_bit<DK1.a, DK1.b>(j0)       ? 0.f : 2.0f * a0;
    a1 = drop_bit<DK1.a, DK1.b>(j0 + 32u) ? 0.f : 2.0f * a1;
    float ss = a0 * a0 + a1 * a1;
#pragma unroll
    for (int o = 16; o > 0; o >>= 1)
        ss += __shfl_xor_sync(0xffffffffu, ss, o);
    float scale = 1.0f / fmaxf(sqrtf(ss), 1e-12f);
    out[node * 64 + lane]      = a0 * scale;
    out[node * 64 + 32 + lane] = a1 * scale;
}

// ---------------- launch ----------------------------------------------------
extern "C" void kernel_launch(void* const* d_in, const int* in_sizes, int n_in,
                              void* d_out, int out_size) {
    const float*    x   = (const float*)d_in[0];
    const uint32_t* ei  = (const uint32_t*)d_in[1];   // int32 or int64 (detected)
    const float*    W1l = (const float*)d_in[2];
    const float*    b1  = (const float*)d_in[3];
    const float*    W1r = (const float*)d_in[4];
    const float*    W2l = (const float*)d_in[5];
    const float*    b2  = (const float*)d_in[6];
    const float*    W2r = (const float*)d_in[7];
    float* out = (float*)d_out;

    k_detect<<<1, 32>>>(ei);
    k_pre<<<N_NODES / 8, 256>>>(x, W1l, W1r);          // 12500 blocks
    k_prep<<<(N_EDGES + 255) / 256, 256>>>(ei);        // 6250 blocks
    k_scan_a<<<NSCAN_BLKS, SCAN_BLK>>>();
    k_scan_b<<<1, 256>>>();
    k_scan_c<<<NSCAN_BLKS, SCAN_BLK>>>();
    k_bucket<<<(N_EDGES + 255) / 256, 256>>>();        // 6250 blocks
    k_agg1<<<N_NODES / 8, 256>>>(b1);                  // 12500 blocks
    k_agg2<<<N_NODES / 8, 256>>>(W2l, b2, W2r, out);   // 12500 blocks
}